// round 15
// baseline (speedup 1.0000x reference)
#include <cuda_runtime.h>
#include <cuda_fp16.h>
#include <cstdint>

#define NTT   365
#define NGRID 2048
#define NX    16
#define NH    256
#define NG    1024
#define CELLS 32
#define NBLK  (NGRID/CELLS)    /* 64 */
#define ROWS  (NTT*NGRID)      /* 747520 */

// ---------------------------------------------------------------------------
// Device-global scratch (~1.54 GB total; must stay < 2 GB for host link)
// ---------------------------------------------------------------------------
__device__ __half g_xg[(size_t)ROWS * NG];   // 1.53 GB fp16 xg for ALL steps
__device__ uint4 g_qih[NG * 32];             // w_ih records [n][kb2][t]   (512KB)
__device__ uint4 g_qhh[NG * 32];             // w_hh records [kb2][n][t]   (512KB)
__device__ float g_bias2[NG];

// ---------------------------------------------------------------------------
// PTX helpers (sm_100 baseline-safe)
// ---------------------------------------------------------------------------
__device__ __forceinline__ uint32_t su32(const void* p) {
    uint32_t a;
    asm("{ .reg .u64 t; cvta.to.shared.u64 t, %1; cvt.u32.u64 %0, t; }" : "=r"(a) : "l"(p));
    return a;
}
__device__ __forceinline__ void mma_f16(float& c0, float& c1, float& c2, float& c3,
                                        uint32_t a0, uint32_t a1, uint32_t a2, uint32_t a3,
                                        uint32_t b0, uint32_t b1) {
    asm volatile(
        "mma.sync.aligned.m16n8k16.row.col.f32.f16.f16.f32 "
        "{%0,%1,%2,%3},{%4,%5,%6,%7},{%8,%9},{%0,%1,%2,%3};"
        : "+f"(c0), "+f"(c1), "+f"(c2), "+f"(c3)
        : "r"(a0), "r"(a1), "r"(a2), "r"(a3), "r"(b0), "r"(b1));
}
__device__ __forceinline__ void ldmat4(uint32_t* r, uint32_t addr) {
    asm volatile("ldmatrix.sync.aligned.m8n8.x4.shared.b16 {%0,%1,%2,%3},[%4];"
                 : "=r"(r[0]), "=r"(r[1]), "=r"(r[2]), "=r"(r[3]) : "r"(addr));
}
__device__ __forceinline__ void cpa16(uint32_t s, const void* g) {
    asm volatile("cp.async.cg.shared.global [%0],[%1],16;" :: "r"(s), "l"(g));
}
#define CPA_COMMIT() asm volatile("cp.async.commit_group;" ::: "memory")
template<int N> __device__ __forceinline__ void cpa_wait() {
    asm volatile("cp.async.wait_group %0;" :: "n"(N) : "memory");
}

__device__ __forceinline__ uint32_t pkh2(float a, float b) {
    __half2 h = __floats2half2_rn(a, b);
    return *(uint32_t*)&h;
}
__device__ __forceinline__ float tanha(float x) {
    float y; asm("tanh.approx.f32 %0, %1;" : "=f"(y) : "f"(x)); return y;
}
__device__ __forceinline__ float sigf(float x) {
    return fmaf(tanha(0.5f * x), 0.5f, 0.5f);
}

// ---------------------------------------------------------------------------
// Kernel 0: pack fp16 weight records + fold bias.  (R14-identical)
// ---------------------------------------------------------------------------
__global__ void prep_kernel(const float* __restrict__ w_ih, const float* __restrict__ w_hh,
                            const float* __restrict__ b_ih, const float* __restrict__ b_hh) {
    int idx = blockIdx.x * blockDim.x + threadIdx.x;   // 32768
    if (idx >= NG * 32) return;
    int n = idx >> 5, kb2 = (idx >> 2) & 7, t = idx & 3;
    int k0 = kb2 * 32 + 2 * t;
#pragma unroll
    for (int w = 0; w < 2; w++) {
        const float* src = (w ? w_hh : w_ih) + n * NH;
        uint4 q;
        q.x = pkh2(src[k0],      src[k0 + 1]);
        q.y = pkh2(src[k0 + 8],  src[k0 + 9]);
        q.z = pkh2(src[k0 + 16], src[k0 + 17]);
        q.w = pkh2(src[k0 + 24], src[k0 + 25]);
        if (w) g_qhh[kb2 * 4096 + n * 4 + t] = q;
        else   g_qih[idx] = q;
    }
    if (idx < NG) g_bias2[idx] = b_ih[idx] + b_hh[idx];
}

// ---------------------------------------------------------------------------
// Kernel 1: fused input + xg GEMM (single-term fp16 mma.sync). R14-identical.
// ---------------------------------------------------------------------------
#define A_TILE (128 * 528)                        /* 67584 */
#define G_SMEM (A_TILE + 8192 + 256 * 17 * 4)     /* 93184 */

__global__ void __launch_bounds__(512, 1) xg_gemm_kernel(const float* __restrict__ x,
                                                         const float* __restrict__ w_in,
                                                         const float* __restrict__ b_in) {
    extern __shared__ char sm[];
    char*  A0 = sm;
    float* xs = (float*)(sm + A_TILE);             // [128][16]
    float* ws = (float*)(sm + A_TILE + 8192);      // [256][17], last = bias
    int tid = threadIdx.x, lane = tid & 31, w = tid >> 5;
    int wm = w >> 2, wn = w & 3;
    int g = lane >> 2, t = lane & 3;
    size_t m0 = (size_t)blockIdx.x * 128;

    ((uint4*)xs)[tid] = ((const uint4*)(x + m0 * NX))[tid];
    {
        int h = tid >> 1, i0 = (tid & 1) * 8;
        const float* src = w_in + h * NX + i0;
#pragma unroll
        for (int i = 0; i < 8; i++) ws[h * 17 + i0 + i] = src[i];
        if ((tid & 1) == 0) ws[h * 17 + 16] = b_in[h];
    }
    __syncthreads();

    for (int it = 0; it < 64; it++) {
        int idx = it * 512 + tid, r = idx >> 8, h = idx & 255;
        float acc = ws[h * 17 + 16];
#pragma unroll
        for (int i = 0; i < 16; i++) acc += xs[r * 16 + i] * ws[h * 17 + i];
        *(__half*)(A0 + r * 528 + h * 2) = __float2half(fmaxf(acc, 0.f));
    }
    __syncthreads();

    uint32_t lbase = (uint32_t)((wm * 32 + (lane & 15)) * 528 + (lane >> 4) * 16);
    uint32_t a0b = su32(A0) + lbase;

    for (int nt = 0; nt < 8; nt++) {
        float acc[2][4][4];
#pragma unroll
        for (int mt = 0; mt < 2; mt++)
#pragma unroll
            for (int nb = 0; nb < 4; nb++)
#pragma unroll
                for (int r = 0; r < 4; r++) acc[mt][nb][r] = 0.f;

        unsigned bofs[4];
#pragma unroll
        for (int nb = 0; nb < 4; nb++)
            bofs[nb] = (unsigned)((nt * 128 + wn * 32 + nb * 8 + g) * 32 + t);

#pragma unroll
        for (int kb = 0; kb < 16; kb += 2) {
            uint32_t af[2][4], ag[2][4];
#pragma unroll
            for (int mt = 0; mt < 2; mt++) {
                ldmat4(af[mt], a0b + mt * 16 * 528 + kb * 32);
                ldmat4(ag[mt], a0b + mt * 16 * 528 + (kb + 1) * 32);
            }
            uint4 Bq[4];
#pragma unroll
            for (int nb = 0; nb < 4; nb++)
                Bq[nb] = g_qih[bofs[nb] + (kb >> 1) * 4];
#pragma unroll
            for (int mt = 0; mt < 2; mt++)
#pragma unroll
                for (int nb = 0; nb < 4; nb++) {
                    mma_f16(acc[mt][nb][0], acc[mt][nb][1], acc[mt][nb][2], acc[mt][nb][3],
                            af[mt][0], af[mt][1], af[mt][2], af[mt][3], Bq[nb].x, Bq[nb].y);
                    mma_f16(acc[mt][nb][0], acc[mt][nb][1], acc[mt][nb][2], acc[mt][nb][3],
                            ag[mt][0], ag[mt][1], ag[mt][2], ag[mt][3], Bq[nb].z, Bq[nb].w);
                }
        }

#pragma unroll
        for (int nb = 0; nb < 4; nb++) {
            int col = nt * 128 + wn * 32 + nb * 8 + 2 * t;
            float2 bs = *(const float2*)(g_bias2 + col);
#pragma unroll
            for (int mt = 0; mt < 2; mt++) {
                size_t row = m0 + wm * 32 + mt * 16 + g;
                *(__half2*)(g_xg + row * NG + col) =
                    __floats2half2_rn(acc[mt][nb][0] + bs.x, acc[mt][nb][1] + bs.y);
                *(__half2*)(g_xg + (row + 8) * NG + col) =
                    __floats2half2_rn(acc[mt][nb][2] + bs.x, acc[mt][nb][3] + bs.y);
            }
        }
    }
}

// ---------------------------------------------------------------------------
// Kernel 2: full 365-step scan, 64 CTAs x 32 cells x 512 thr (16 warps).
// Weights via per-warp cp.async ping-pong (R14 pipeline); xg single-buffered
// (read only at init; re-staged for t+1 after a post-init barrier) with
// per-row chunk rotation for conflict-free init reads. Chip weight traffic
// halves vs 128 CTAs.
// ---------------------------------------------------------------------------
#define XGB  (CELLS * 2048)             /* 65536: xg buffer (rotated rows) */
#define S_HS XGB                        /* 65536 */
#define HSB  (CELLS * 528)              /* 16896: one fp16 h tile (32 rows) */
#define S_RED (S_HS + 2 * HSB)          /* 99328 */
#define S_W   (S_RED + 2048)            /* 101376: weight stages */
#define S_SMEM (S_W + 16 * 2 * 4096)    /* 232448 == max dyn smem */

__global__ void __launch_bounds__(512, 1) lstm_scan(const float* __restrict__ w_out,
                                                    const float* __restrict__ b_out,
                                                    float* __restrict__ out) {
    extern __shared__ char sm[];
    float* red = (float*)(sm + S_RED);
    int tid = threadIdx.x, lane = tid & 31, w = tid >> 5;
    int g = lane >> 2, t = lane & 3;
    int b0 = blockIdx.x * CELLS;

    // zero h tile (buffer 0); c-state in regs
    for (int i = tid; i < HSB / 4; i += 512) ((uint32_t*)(sm + S_HS))[i] = 0;
    float cst[16];
#pragma unroll
    for (int i = 0; i < 16; i++) cst[i] = 0.f;

    // per-warp weight stage bases
    uint32_t wsb = su32(sm) + S_W + w * 8192;
    const char* wsm = sm + S_W + w * 8192;
    unsigned cb[8];
#pragma unroll
    for (int j = 0; j < 8; j++)
        cb[j] = (unsigned)((j >> 1) * 1024 + w * 64 + (j & 1) * 32 + lane);

#define W_COPY(slot, kb2s) do { \
    _Pragma("unroll") \
    for (int j = 0; j < 8; j++) \
        cpa16(wsb + (slot) * 4096 + j * 512 + lane * 16, \
              (const void*)(g_qhh + (kb2s) * 4096 + cb[j])); \
    CPA_COMMIT(); } while (0)

// xg copy with per-row chunk rotation: chunk j of row r lands at (j + (r&7))&127
#define XG_COPY(stp) do { \
    const char* src = (const char*)(g_xg + ((size_t)(stp) * NGRID + b0) * NG); \
    uint32_t dst = su32(sm); \
    for (int c = tid; c < 4096; c += 512) { \
        int r_ = c >> 7, j_ = c & 127; \
        cpa16(dst + r_ * 2048 + (((j_ + (r_ & 7)) & 127) << 4), src + c * 16); \
    } \
    CPA_COMMIT(); } while (0)

    // prefetch xg step 0
    XG_COPY(0);

    float2 wo[2];
#pragma unroll
    for (int nb = 0; nb < 2; nb++) wo[nb] = *(const float2*)(w_out + w * 16 + nb * 8 + 2 * t);
    float bout = b_out[0];

    uint32_t hlbase = (uint32_t)((lane & 15) * 528 + (lane >> 4) * 16);

    for (int st = 0; st < NTT; st++) {
        cpa_wait<0>();
        __syncthreads();
        int rb = st & 1, wb = rb ^ 1;

        // start weight pipeline for this step
        W_COPY(0, 0);
        W_COPY(1, 1);

        // accumulator init = xg (fp16 -> f32), rotated-chunk addressing
        float acc[4][2][2][4];   // [G][mt][nb][r]
#pragma unroll
        for (int G = 0; G < 4; G++)
#pragma unroll
            for (int mt = 0; mt < 2; mt++)
#pragma unroll
                for (int nb = 0; nb < 2; nb++) {
                    int chunk = G * 32 + w * 2 + nb;
#pragma unroll
                    for (int rh = 0; rh < 2; rh++) {
                        int row = mt * 16 + rh * 8 + g;
                        int nc = (chunk + (row & 7)) & 127;
                        float2 f = __half22float2(
                            *(__half2*)(sm + row * 2048 + nc * 16 + 4 * t));
                        acc[G][mt][nb][rh * 2]     = f.x;
                        acc[G][mt][nb][rh * 2 + 1] = f.y;
                    }
                }
        __syncthreads();   // all init reads done before xg re-stage writes land

        uint32_t h0b = su32(sm) + S_HS + rb * HSB + hlbase;

#define KB_CONSUME(kb2c, WGN) do { \
    uint32_t a[2][2][4]; \
    _Pragma("unroll") \
    for (int mt = 0; mt < 2; mt++) { \
        ldmat4(a[mt][0], h0b + mt * 16 * 528 + (2 * (kb2c)) * 32); \
        ldmat4(a[mt][1], h0b + mt * 16 * 528 + (2 * (kb2c) + 1) * 32); \
    } \
    cpa_wait<WGN>(); \
    const char* wslot = wsm + ((kb2c) & 1) * 4096; \
    _Pragma("unroll") \
    for (int G = 0; G < 4; G++) \
    _Pragma("unroll") \
    for (int nb = 0; nb < 2; nb++) { \
        uint4 Bq = *(const uint4*)(wslot + (G * 2 + nb) * 512 + lane * 16); \
        _Pragma("unroll") \
        for (int mt = 0; mt < 2; mt++) { \
            float* c4 = acc[G][mt][nb]; \
            mma_f16(c4[0], c4[1], c4[2], c4[3], \
                    a[mt][0][0], a[mt][0][1], a[mt][0][2], a[mt][0][3], Bq.x, Bq.y); \
            mma_f16(c4[0], c4[1], c4[2], c4[3], \
                    a[mt][1][0], a[mt][1][1], a[mt][1][2], a[mt][1][3], Bq.z, Bq.w); \
        } \
    } } while (0)

        // commit order: W0,W1,[k0]W2,[k1]W3,X,[k2]W4,[k3]W5,[k4]W6,[k5]W7
        KB_CONSUME(0, 1);  W_COPY(0, 2);
        KB_CONSUME(1, 1);  W_COPY(1, 3);
        {   // next step's xg into the SAME buffer (safe: init barrier passed)
            int pf = (st + 1 < NTT) ? st + 1 : st;
            XG_COPY(pf);
        }
        KB_CONSUME(2, 2);  W_COPY(0, 4);
        KB_CONSUME(3, 2);  W_COPY(1, 5);
        KB_CONSUME(4, 1);  W_COPY(0, 6);
        KB_CONSUME(5, 1);  W_COPY(1, 7);
        KB_CONSUME(6, 1);
        KB_CONSUME(7, 0);
#undef KB_CONSUME

        // pointwise cell + h restage + fused output partials
        char* hw0 = sm + S_HS + wb * HSB;
        float p[4] = {0.f, 0.f, 0.f, 0.f};
#pragma unroll
        for (int mt = 0; mt < 2; mt++)
#pragma unroll
            for (int nb = 0; nb < 2; nb++) {
                int j0 = w * 16 + nb * 8 + 2 * t;
#pragma unroll
                for (int rh = 0; rh < 2; rh++) {
                    int r0 = rh * 2;
                    int row = mt * 16 + rh * 8 + g;
                    int ci = ((mt * 2 + rh) * 2 + nb) * 2;
                    float i0 = sigf(acc[0][mt][nb][r0]),      f0 = sigf(acc[1][mt][nb][r0]);
                    float g0 = tanha(acc[2][mt][nb][r0]),     o0 = sigf(acc[3][mt][nb][r0]);
                    float i1 = sigf(acc[0][mt][nb][r0 + 1]),  f1 = sigf(acc[1][mt][nb][r0 + 1]);
                    float g1 = tanha(acc[2][mt][nb][r0 + 1]), o1 = sigf(acc[3][mt][nb][r0 + 1]);
                    float& cA = cst[ci];     cA = f0 * cA + i0 * g0;
                    float& cB = cst[ci + 1]; cB = f1 * cB + i1 * g1;
                    float hA = o0 * tanha(cA), hB = o1 * tanha(cB);
                    p[mt * 2 + rh] += hA * wo[nb].x + hB * wo[nb].y;
                    *(uint32_t*)(hw0 + row * 528 + j0 * 2) = pkh2(hA, hB);
                }
            }
#pragma unroll
        for (int q = 0; q < 4; q++) {
            p[q] += __shfl_xor_sync(0xffffffffu, p[q], 1);
            p[q] += __shfl_xor_sync(0xffffffffu, p[q], 2);
        }
        if (t == 0) {
            red[(g)      * 16 + w] = p[0];
            red[(g + 8)  * 16 + w] = p[1];
            red[(g + 16) * 16 + w] = p[2];
            red[(g + 24) * 16 + w] = p[3];
        }
        __syncthreads();
        if (tid < 32) {
            float s = bout;
#pragma unroll
            for (int k = 0; k < 16; k++) s += red[tid * 16 + k];
            out[(size_t)st * NGRID + b0 + tid] = s;
        }
    }
#undef W_COPY
#undef XG_COPY
}

// ---------------------------------------------------------------------------
extern "C" void kernel_launch(void* const* d_in, const int* in_sizes, int n_in,
                              void* d_out, int out_size) {
    const float* x     = (const float*)d_in[0];
    const float* w_in  = (const float*)d_in[1];
    const float* b_in  = (const float*)d_in[2];
    const float* w_ih  = (const float*)d_in[3];
    const float* w_hh  = (const float*)d_in[4];
    const float* b_ih  = (const float*)d_in[5];
    const float* b_hh  = (const float*)d_in[6];
    const float* w_out = (const float*)d_in[7];
    const float* b_out = (const float*)d_in[8];
    float* out = (float*)d_out;

    cudaFuncSetAttribute(xg_gemm_kernel, cudaFuncAttributeMaxDynamicSharedMemorySize, G_SMEM);
    cudaFuncSetAttribute(lstm_scan,      cudaFuncAttributeMaxDynamicSharedMemorySize, S_SMEM);

    prep_kernel<<<(NG * 32 + 255) / 256, 256>>>(w_ih, w_hh, b_ih, b_hh);
    xg_gemm_kernel<<<ROWS / 128, 512, G_SMEM>>>(x, w_in, b_in);
    lstm_scan<<<NBLK, 512, S_SMEM>>>(w_out, b_out, out);
}